// round 6
// baseline (speedup 1.0000x reference)
#include <cuda_runtime.h>
#include <cstdint>

#define NN   100000
#define EE   1600000
#define NB_SCAN 391   // ceil(NN/256)

// ---------------- scratch (static device globals; no allocation) ----------------
__device__ __align__(16) float g_h[(size_t)NN * 128];     // post-GEMM activations
__device__ __align__(16) float g_agg[(size_t)NN * 128];   // aggregated layer output
__device__ int   g_deg[NN];          // in-degree of each destination node (row)
__device__ int   g_cur[NN];          // placement cursor
__device__ float g_dis[NN];          // (deg+1)^{-1/2}
__device__ int   g_start[NN + 1];    // CSR row offsets
__device__ int   g_part[NB_SCAN];    // scan partials
__device__ int   g_col[EE];          // CSR: source node per edge
__device__ float g_norm[EE];         // CSR: edge weight
__device__ int   g_is64;             // edge_index dtype flag

// ---------------- edge dtype detection ----------------
// If int64 with values < 2^17, every high word is 0. If int32, ull-words pair
// two indices and high words are nonzero almost everywhere.
__global__ void k_dtype(const unsigned long long* __restrict__ ei) {
    __shared__ int bad;
    if (threadIdx.x == 0) bad = 0;
    __syncthreads();
    for (int t = threadIdx.x; t < 4096; t += 256)
        if (ei[t] >> 32) bad = 1;          // benign race
    __syncthreads();
    if (threadIdx.x == 0) g_is64 = bad ? 0 : 1;
}

__device__ __forceinline__ unsigned edge_val(const void* ei, int pos) {
    if (g_is64) return (unsigned)((const long long*)ei)[pos];
    return (unsigned)((const int*)ei)[pos];
}

// ---------------- graph precompute ----------------
__global__ void k_zero() {
    int i = blockIdx.x * blockDim.x + threadIdx.x;
    if (i < NN) { g_deg[i] = 0; g_cur[i] = 0; }
}

__global__ void k_zero_edges() {
    int e = blockIdx.x * blockDim.x + threadIdx.x;
    if (e < EE) { g_col[e] = 0; g_norm[e] = 0.0f; }
}

__global__ void k_count(const void* __restrict__ ei) {
    int e = blockIdx.x * blockDim.x + threadIdx.x;
    if (e < EE) {
        unsigned r = edge_val(ei, e);
        if (r < NN) atomicAdd(&g_deg[r], 1);   // guarded: no wild atomics
    }
}

__global__ void k_dis() {
    int i = blockIdx.x * blockDim.x + threadIdx.x;
    if (i < NN) g_dis[i] = rsqrtf((float)g_deg[i] + 1.0f);
}

// exclusive scan of g_deg -> g_start, 3 phases
__global__ void k_scan1() {
    __shared__ int s[256];
    int t = threadIdx.x;
    int i = blockIdx.x * 256 + t;
    int v = (i < NN) ? g_deg[i] : 0;
    s[t] = v;
    __syncthreads();
#pragma unroll
    for (int off = 1; off < 256; off <<= 1) {
        int x = (t >= off) ? s[t - off] : 0;
        __syncthreads();
        s[t] += x;
        __syncthreads();
    }
    if (i < NN) g_start[i] = s[t] - v;      // exclusive within block
    if (t == 255) g_part[blockIdx.x] = s[255];
}

__global__ void k_scan2() {
    __shared__ int s[512];
    int t = threadIdx.x;
    int v = (t < NB_SCAN) ? g_part[t] : 0;
    s[t] = v;
    __syncthreads();
#pragma unroll
    for (int off = 1; off < 512; off <<= 1) {
        int x = (t >= off) ? s[t - off] : 0;
        __syncthreads();
        s[t] += x;
        __syncthreads();
    }
    if (t < NB_SCAN) g_part[t] = s[t] - v;  // exclusive
}

__global__ void k_scan3() {
    int i = blockIdx.x * blockDim.x + threadIdx.x;
    if (i < NN) g_start[i] += g_part[i >> 8];
    if (i == 0) g_start[NN] = EE;
}

__global__ void k_place(const void* __restrict__ ei) {
    int e = blockIdx.x * blockDim.x + threadIdx.x;
    if (e < EE) {
        unsigned r = edge_val(ei, e);
        unsigned c = edge_val(ei, EE + e);
        if (r < NN && c < NN) {
            int pos = g_start[r] + atomicAdd(&g_cur[r], 1);
            g_col[pos]  = (int)c;
            g_norm[pos] = g_dis[r] * g_dis[c];
        }
    }
}

// ---------------- SGEMM: g_h[M,Nc] = act(A[M,128]) @ B[128,Nc] ----------------
template <bool RELU, bool A_FROM_AGG>
__global__ __launch_bounds__(256) void k_sgemm(
    const float* __restrict__ Aext, const float* __restrict__ B, int Nc)
{
    constexpr int BM = 128, BK = 16, TM = 8, TN = 4;
    const int K = 128;
    const float* A = A_FROM_AGG ? (const float*)g_agg : Aext;

    __shared__ float As[BK][BM];
    __shared__ float Bs[BK][64];

    const int tid = threadIdx.x;
    const int m0  = blockIdx.x * BM;
    const int n0  = blockIdx.y * 64;
    const int ty  = tid >> 4;
    const int tx  = tid & 15;

    float acc[TM][TN];
#pragma unroll
    for (int i = 0; i < TM; i++)
#pragma unroll
        for (int j = 0; j < TN; j++) acc[i][j] = 0.0f;

    for (int k0 = 0; k0 < K; k0 += BK) {
#pragma unroll
        for (int l = 0; l < 2; l++) {
            int f   = tid + l * 256;
            int row = f >> 2;
            int kq  = f & 3;
            float4 v = make_float4(0.f, 0.f, 0.f, 0.f);
            if (m0 + row < NN)
                v = *(const float4*)(A + (size_t)(m0 + row) * K + k0 + kq * 4);
            if (RELU) {
                v.x = fmaxf(v.x, 0.f); v.y = fmaxf(v.y, 0.f);
                v.z = fmaxf(v.z, 0.f); v.w = fmaxf(v.w, 0.f);
            }
            As[kq * 4 + 0][row] = v.x;
            As[kq * 4 + 1][row] = v.y;
            As[kq * 4 + 2][row] = v.z;
            As[kq * 4 + 3][row] = v.w;
        }
#pragma unroll
        for (int l = 0; l < 4; l++) {
            int f  = tid + l * 256;
            int kk = f >> 6;
            int n  = f & 63;
            float v = 0.0f;
            if (n0 + n < Nc) v = B[(size_t)(k0 + kk) * Nc + n0 + n];
            Bs[kk][n] = v;
        }
        __syncthreads();

#pragma unroll
        for (int k = 0; k < BK; k++) {
            float4 a0 = *(const float4*)&As[k][ty * TM];
            float4 a1 = *(const float4*)&As[k][ty * TM + 4];
            float4 bv = *(const float4*)&Bs[k][tx * TN];
            float a[TM] = {a0.x, a0.y, a0.z, a0.w, a1.x, a1.y, a1.z, a1.w};
            float b[TN] = {bv.x, bv.y, bv.z, bv.w};
#pragma unroll
            for (int i = 0; i < TM; i++)
#pragma unroll
                for (int j = 0; j < TN; j++)
                    acc[i][j] = fmaf(a[i], b[j], acc[i][j]);
        }
        __syncthreads();
    }

#pragma unroll
    for (int i = 0; i < TM; i++) {
        int m = m0 + ty * TM + i;
        if (m < NN) {
#pragma unroll
            for (int j = 0; j < TN; j++) {
                int n = n0 + tx * TN + j;
                if (n < Nc) g_h[(size_t)m * Nc + n] = acc[i][j];
            }
        }
    }
}

// ---------------- aggregation: warp-per-node CSR gather ----------------
// agg[i] = dis[i]^2 * h[i] + b + sum_{j in CSR(i)} norm[j] * h[col[j]]
__global__ __launch_bounds__(256) void k_agg128(const float* __restrict__ b) {
    int w    = (blockIdx.x * blockDim.x + threadIdx.x) >> 5;
    int lane = threadIdx.x & 31;
    if (w >= NN) return;

    const float4* hv = (const float4*)g_h;
    int   s = g_start[w];
    int   e = g_start[w + 1];
    float d = g_dis[w];
    float dd = d * d;

    float4 acc = hv[(size_t)w * 32 + lane];
    acc.x = dd * acc.x + b[lane * 4 + 0];
    acc.y = dd * acc.y + b[lane * 4 + 1];
    acc.z = dd * acc.z + b[lane * 4 + 2];
    acc.w = dd * acc.w + b[lane * 4 + 3];

    for (int j = s; j < e; j++) {
        unsigned c = (unsigned)g_col[j];
        if (c >= NN) c = 0;                        // safety clamp
        float wn = g_norm[j];
        float4 v = hv[(size_t)c * 32 + lane];
        acc.x = fmaf(wn, v.x, acc.x);
        acc.y = fmaf(wn, v.y, acc.y);
        acc.z = fmaf(wn, v.z, acc.z);
        acc.w = fmaf(wn, v.w, acc.w);
    }
    ((float4*)g_agg)[(size_t)w * 32 + lane] = acc;
}

__global__ __launch_bounds__(256) void k_agg47(const float* __restrict__ b,
                                               float* __restrict__ out) {
    int w    = (blockIdx.x * blockDim.x + threadIdx.x) >> 5;
    int lane = threadIdx.x & 31;
    if (w >= NN) return;

    int   s = g_start[w];
    int   e = g_start[w + 1];
    float d = g_dis[w];
    float dd = d * d;
    bool  hi = (lane < 15);   // channels 32..46

    float acc0 = dd * g_h[(size_t)w * 47 + lane] + b[lane];
    float acc1 = hi ? (dd * g_h[(size_t)w * 47 + 32 + lane] + b[32 + lane]) : 0.0f;

    for (int j = s; j < e; j++) {
        unsigned c = (unsigned)g_col[j];
        if (c >= NN) c = 0;                        // safety clamp
        float wn = g_norm[j];
        acc0 = fmaf(wn, g_h[(size_t)c * 47 + lane], acc0);
        if (hi) acc1 = fmaf(wn, g_h[(size_t)c * 47 + 32 + lane], acc1);
    }
    out[(size_t)w * 47 + lane] = acc0;
    if (hi) out[(size_t)w * 47 + 32 + lane] = acc1;
}

// ---------------- launch ----------------
extern "C" void kernel_launch(void* const* d_in, const int* in_sizes, int n_in,
                              void* d_out, int out_size) {
    // ---- size-driven input identification (element counts) ----
    // x: 12,800,000   edge_index: 3,200,000   edge_attr: 12,800,000
    // W1/W2: 16,384   b1/b2: 128   W3: 6,016   b3: 47
    const void*  ei = 0;
    const float *x = 0, *W1 = 0, *b1 = 0, *W2 = 0, *b2 = 0, *W3 = 0, *b3 = 0;
    int idx_ei = -1;
    int big[4], nbig = 0;      // positions of 12.8M-sized inputs
    int w16[4], nw16 = 0;      // positions of 16384-sized inputs
    int c128[4], nc128 = 0;    // positions of 128-sized inputs
    for (int i = 0; i < n_in; i++) {
        int s = in_sizes[i];
        if (s == 3200000) { idx_ei = i; }
        else if (s == 12800000 && nbig < 4) big[nbig++] = i;
        else if (s == 16384  && nw16 < 4) w16[nw16++] = i;
        else if (s == 128    && nc128 < 4) c128[nc128++] = i;
        else if (s == 6016) W3 = (const float*)d_in[i];
        else if (s == 47)   b3 = (const float*)d_in[i];
    }
    ei = d_in[idx_ei];
    W1 = (const float*)d_in[w16[0]];  W2 = (const float*)d_in[w16[1]];
    b1 = (const float*)d_in[c128[0]]; b2 = (const float*)d_in[c128[1]];
    // x vs edge_attr tie-break: dict order puts x at slot 0 (before edge_index);
    // any other ordering (e.g. alphabetical) puts x after edge_index.
    if (nbig == 2) x = (const float*)((big[0] < idx_ei) ? d_in[big[0]] : d_in[big[1]]);
    else           x = (const float*)d_in[big[0]];

    float* out = (float*)d_out;

    // graph precompute: dtype detect, degrees, norms, CSR
    k_dtype<<<1, 256>>>((const unsigned long long*)ei);
    k_zero <<<NB_SCAN, 256>>>();
    k_zero_edges<<<(EE + 255) / 256, 256>>>();
    k_count<<<(EE + 255) / 256, 256>>>(ei);
    k_dis  <<<NB_SCAN, 256>>>();
    k_scan1<<<NB_SCAN, 256>>>();
    k_scan2<<<1, 512>>>();
    k_scan3<<<NB_SCAN, 256>>>();
    k_place<<<(EE + 255) / 256, 256>>>(ei);

    const dim3 gemm128((NN + 127) / 128, 2);
    const dim3 gemm47((NN + 127) / 128, 1);
    const int  nb_agg = (NN * 32 + 255) / 256;   // warp per node

    // layer 1
    k_sgemm<false, false><<<gemm128, 256>>>(x, W1, 128);
    k_agg128<<<nb_agg, 256>>>(b1);
    // layer 2 (relu fused into GEMM A-load)
    k_sgemm<true, true><<<gemm128, 256>>>(nullptr, W2, 128);
    k_agg128<<<nb_agg, 256>>>(b2);
    // layer 3 (47 outputs, writes d_out)
    k_sgemm<true, true><<<gemm47, 256>>>(nullptr, W3, 47);
    k_agg47<<<nb_agg, 256>>>(b3, out);
}